// round 15
// baseline (speedup 1.0000x reference)
#include <cuda_runtime.h>
#include <cuda_fp16.h>

#define N_NODES 10000
#define N_EDGES 640000
#define D 128
#define BN_EPS 1e-5f
#define GEMM_WARPS 16                    // 8 pairs
#define GEMM_ROWS 8
#define GEMM_GRID 148
#define N_TILES (N_NODES / GEMM_ROWS)    // 1250
#define CAP 256

// Scratch (no allocation allowed anywhere)
__device__ __align__(16) float  g_agg[N_NODES * D];
__device__ __align__(16) float  g_h2[N_NODES * D];
__device__ __align__(16) __half g_xh[N_NODES * D];
__device__ __align__(16) float  g_colsum[D];
__device__ __align__(16) float  g_colsumsq[D];

__device__ int g_deg[N_NODES];
__device__ int g_bucket[N_NODES * CAP];
__device__ int g_tile_ctr;

__device__ int g_ei_sel;
__device__ int g_ei_64;
__device__ int g_gamma_sel;

// ---------------------------------------------------------------------------
__device__ __forceinline__ int edge_at(const void* eip, int i, int is64) {
    return is64 ? (int)((const long long*)eip)[i] : ((const int*)eip)[i];
}
__device__ __forceinline__ int looks_like_idx32(const int* p) {
    #pragma unroll
    for (int i = 0; i < 32; i++) { int v = p[i]; if (v < 0 || v >= N_NODES) return 0; }
    return 1;
}
__device__ __forceinline__ int looks_like_idx64(const long long* p) {
    #pragma unroll
    for (int i = 0; i < 32; i++) { long long v = p[i]; if (v < 0 || v >= N_NODES) return 0; }
    return 1;
}

// ---------------------------------------------------------------------------
// 1) prep
// ---------------------------------------------------------------------------
__global__ void prep_kernel(const void* __restrict__ big0,
                            const void* __restrict__ big1,
                            const float* __restrict__ c0,
                            const float* __restrict__ c1) {
    int i = blockIdx.x * blockDim.x + threadIdx.x;
    if (i < N_NODES) g_deg[i] = 0;
    if (i < D) { g_colsum[i] = 0.f; g_colsumsq[i] = 0.f; }
    if (i == 0) {
        g_tile_ctr = 0;
        if (looks_like_idx32((const int*)big0))            { g_ei_sel = 0; g_ei_64 = 0; }
        else if (looks_like_idx64((const long long*)big0)) { g_ei_sel = 0; g_ei_64 = 1; }
        else if (looks_like_idx32((const int*)big1))       { g_ei_sel = 1; g_ei_64 = 0; }
        else                                               { g_ei_sel = 1; g_ei_64 = 1; }
        int sel = 2;
        if (fabsf(c0[0] - 1.0f) < 0.25f)      sel = 0;
        else if (fabsf(c1[0] - 1.0f) < 0.25f) sel = 1;
        g_gamma_sel = sel;
    }
}

// ---------------------------------------------------------------------------
// 2) fill buckets + convert x->fp16
// ---------------------------------------------------------------------------
__global__ void fill_convert_kernel(const void* __restrict__ big0,
                                    const void* __restrict__ big1) {
    const void*  eip = (g_ei_sel == 0) ? big0 : big1;
    const float* x   = (const float*)((g_ei_sel == 0) ? big1 : big0);
    const int is64 = g_ei_64;
    int e = blockIdx.x * blockDim.x + threadIdx.x;

    const int n4 = N_NODES * D / 4;
    if (e < n4) {
        float4 v = ((const float4*)x)[e];
        __half2 h0 = __floats2half2_rn(v.x, v.y);
        __half2 h1 = __floats2half2_rn(v.z, v.w);
        uint2 packed;
        packed.x = *(unsigned*)&h0;
        packed.y = *(unsigned*)&h1;
        ((uint2*)g_xh)[e] = packed;
    }

    if (e >= N_EDGES) return;
    int s = edge_at(eip, e, is64);
    int d = edge_at(eip, N_EDGES + e, is64);
    s = min(max(s, 0), N_NODES - 1);
    d = min(max(d, 0), N_NODES - 1);
    int pos = atomicAdd(&g_deg[d], 1);
    if (pos < CAP) g_bucket[d * CAP + pos] = s;
}

// ---------------------------------------------------------------------------
// 3) gather (R12-proven, unchanged)
// ---------------------------------------------------------------------------
__global__ void gather_kernel(const void* __restrict__ big0,
                              const void* __restrict__ big1) {
    const float* x = (const float*)((g_ei_sel == 0) ? big1 : big0);
    int warp = (blockIdx.x * blockDim.x + threadIdx.x) >> 5;
    int lane = threadIdx.x & 31;
    if (warp >= N_NODES) return;
    const int n   = warp;
    const int cnt = min(g_deg[n], CAP);
    const int* bk = g_bucket + n * CAP;

    float4 acc = ((const float4*)(x + (size_t)n * D))[lane];

    int j = 0;
    for (; j + 32 <= cnt; j += 32) {
        int id = bk[j + lane];
        #pragma unroll
        for (int i = 0; i < 32; i++) {
            int s = __shfl_sync(0xffffffffu, id, i);
            uint2 v = ((const uint2*)(g_xh + (size_t)s * D))[lane];
            float2 f0 = __half22float2(*(__half2*)&v.x);
            float2 f1 = __half22float2(*(__half2*)&v.y);
            acc.x += f0.x; acc.y += f0.y; acc.z += f1.x; acc.w += f1.y;
        }
    }
    if (j < cnt) {
        int rem = cnt - j;
        int id = bk[j + min(lane, rem - 1)];
        for (int i = 0; i < rem; i++) {
            int s = __shfl_sync(0xffffffffu, id, i);
            uint2 v = ((const uint2*)(g_xh + (size_t)s * D))[lane];
            float2 f0 = __half22float2(*(__half2*)&v.x);
            float2 f1 = __half22float2(*(__half2*)&v.y);
            acc.x += f0.x; acc.y += f0.y; acc.z += f1.x; acc.w += f1.y;
        }
    }
    ((float4*)(g_agg + (size_t)n * D))[lane] = acc;
}

// ---------------------------------------------------------------------------
// 4) GEMM, k-split warp pairs: even warp k[0:64), odd warp k[64:128)
//    16 warps/block, all active (2500 warp-jobs), ROWS=8 FFMA density.
// ---------------------------------------------------------------------------
__device__ __forceinline__ float4 f4fma(float4 a, float s, float4 w) {
    a.x += s * w.x; a.y += s * w.y; a.z += s * w.z; a.w += s * w.w; return a;
}
__device__ __forceinline__ void pair_bar(int pair) {
    asm volatile("bar.sync %0, 64;" :: "r"(pair + 1) : "memory");
}

// smem float offsets
#define SM_W     0
#define SM_RB    (D * D)                         // 16 warps * 512 floats
#define SM_SC    (SM_RB + GEMM_WARPS * 512)      // 8 pairs * 1024 floats
#define SM_TID   (SM_SC + (GEMM_WARPS / 2) * 1024)
#define SM_TOTAL (SM_TID + GEMM_WARPS / 2)

__global__ void __launch_bounds__(GEMM_WARPS * 32)
gemm_kernel(const float* __restrict__ W,
            const float* __restrict__ c0,
            const float* __restrict__ c1,
            const float* __restrict__ c2) {
    const int gs = g_gamma_sel;
    const float* b = (gs == 0) ? c1 : c0;

    extern __shared__ float smem[];
    float4* Wsh4 = (float4*)(smem + SM_W);
    const int lane = threadIdx.x & 31;
    const int warp = threadIdx.x >> 5;
    const int pair = warp >> 1;
    const int h    = warp & 1;                   // k-half
    float4* rb4 = (float4*)(smem + SM_RB) + warp * 128;   // private 8x64 floats
    float4* sc4 = (float4*)(smem + SM_SC) + pair * 256;   // pair scratch 8x128
    int* tids   = (int*)(smem + SM_TID);

    for (int i = threadIdx.x; i < D * D / 4; i += blockDim.x)
        Wsh4[i] = ((const float4*)W)[i];
    __syncthreads();

    const float4 bias = ((const float4*)b)[lane];
    float4 ssum = make_float4(0.f, 0.f, 0.f, 0.f);
    float4 ssq  = make_float4(0.f, 0.f, 0.f, 0.f);

    for (;;) {
        if (h == 0 && lane == 0) tids[pair] = atomicAdd(&g_tile_ctr, 1);
        pair_bar(pair);                           // barA: tid ready, scratch free
        const int tile = tids[pair];
        if (tile >= N_TILES) break;
        const int r0 = tile * GEMM_ROWS;

        // stage own k-half of 8 rows: 128 float4, 4 per lane
        #pragma unroll
        for (int q = 0; q < 4; q++) {
            int idx = lane + 32 * q;
            int r = idx >> 4, k4l = idx & 15;
            rb4[r * 16 + k4l] =
                ((const float4*)(g_agg + (size_t)(r0 + r) * D))[h * 16 + k4l];
        }
        __syncwarp();

        float4 acc[GEMM_ROWS];
        #pragma unroll
        for (int r = 0; r < GEMM_ROWS; r++) acc[r] = make_float4(0.f, 0.f, 0.f, 0.f);

        const int kb0 = h * 64;
        #pragma unroll 4
        for (int k4l = 0; k4l < 16; k4l++) {
            float4 w0 = Wsh4[(kb0 + 4 * k4l + 0) * 32 + lane];
            float4 w1 = Wsh4[(kb0 + 4 * k4l + 1) * 32 + lane];
            float4 w2 = Wsh4[(kb0 + 4 * k4l + 2) * 32 + lane];
            float4 w3 = Wsh4[(kb0 + 4 * k4l + 3) * 32 + lane];
            #pragma unroll
            for (int r = 0; r < GEMM_ROWS; r++) {
                float4 a = rb4[r * 16 + k4l];
                acc[r] = f4fma(acc[r], a.x, w0);
                acc[r] = f4fma(acc[r], a.y, w1);
                acc[r] = f4fma(acc[r], a.z, w2);
                acc[r] = f4fma(acc[r], a.w, w3);
            }
        }

        if (h == 0) {
            #pragma unroll
            for (int r = 0; r < GEMM_ROWS; r++) sc4[r * 32 + lane] = acc[r];
            pair_bar(pair);                       // barB: partial published
        } else {
            pair_bar(pair);                       // barB
            #pragma unroll
            for (int r = 0; r < GEMM_ROWS; r++) {
                float4 p = sc4[r * 32 + lane];
                float4 o;
                o.x = fmaxf(acc[r].x + p.x + bias.x, 0.f);
                o.y = fmaxf(acc[r].y + p.y + bias.y, 0.f);
                o.z = fmaxf(acc[r].z + p.z + bias.z, 0.f);
                o.w = fmaxf(acc[r].w + p.w + bias.w, 0.f);
                ((float4*)(g_h2 + (size_t)(r0 + r) * D))[lane] = o;
                ssum.x += o.x; ssum.y += o.y; ssum.z += o.z; ssum.w += o.w;
                ssq.x  += o.x * o.x; ssq.y += o.y * o.y;
                ssq.z  += o.z * o.z; ssq.w += o.w * o.w;
            }
        }
    }

    // even warps contribute zeros — harmless
    atomicAdd(((float4*)g_colsum) + lane, ssum);
    atomicAdd(((float4*)g_colsumsq) + lane, ssq);
}

// ---------------------------------------------------------------------------
// 5) bn: 4 independent float4 per thread (MLP=4)
// ---------------------------------------------------------------------------
#define BN_CHUNK (N_NODES * D / 4 / 4)   // 80000 float4 per chunk
__global__ void bn_kernel(const float* __restrict__ c0,
                          const float* __restrict__ c1,
                          const float* __restrict__ c2,
                          float* __restrict__ out) {
    __shared__ float s_scale[D], s_shift[D];
    const int gs = g_gamma_sel;
    const float* gamma = (gs == 0) ? c0 : (gs == 1) ? c1 : c2;
    const float* beta  = (gs == 2) ? c1 : c2;

    if (threadIdx.x < D) {
        int j = threadIdx.x;
        float mean = g_colsum[j] * (1.0f / N_NODES);
        float var  = g_colsumsq[j] * (1.0f / N_NODES) - mean * mean;
        float sc   = gamma[j] * rsqrtf(var + BN_EPS);
        s_scale[j] = sc;
        s_shift[j] = beta[j] - mean * sc;
    }
    __syncthreads();

    int i = blockIdx.x * blockDim.x + threadIdx.x;
    if (i >= BN_CHUNK) return;
    // BN_CHUNK is a multiple of 32 -> same column indices for all 4 chunks
    int c4 = (i & (D / 4 - 1)) * 4;
    float sx = s_scale[c4 + 0], sy = s_scale[c4 + 1],
          sz = s_scale[c4 + 2], sw = s_scale[c4 + 3];
    float tx = s_shift[c4 + 0], ty = s_shift[c4 + 1],
          tz = s_shift[c4 + 2], tw = s_shift[c4 + 3];
    #pragma unroll
    for (int q = 0; q < 4; q++) {
        int idx = i + q * BN_CHUNK;
        float4 hv = ((const float4*)g_h2)[idx];
        float4 o;
        o.x = hv.x * sx + tx;
        o.y = hv.y * sy + ty;
        o.z = hv.z * sz + tz;
        o.w = hv.w * sw + tw;
        ((float4*)out)[idx] = o;
    }
}

// ---------------------------------------------------------------------------
extern "C" void kernel_launch(void* const* d_in, const int* in_sizes, int n_in,
                              void* d_out, int out_size) {
    const void* big[2] = {nullptr, nullptr};
    const float* W = nullptr;
    const float* small[3] = {nullptr, nullptr, nullptr};
    int nbig = 0, nsmall = 0;
    for (int i = 0; i < n_in; i++) {
        int s = in_sizes[i];
        if (s == D * D) {
            W = (const float*)d_in[i];
        } else if (s == D) {
            if (nsmall < 3) small[nsmall++] = (const float*)d_in[i];
        } else if (s >= N_NODES * D) {
            if (nbig < 2) big[nbig++] = d_in[i];
        }
    }
    float* out = (float*)d_out;

    prep_kernel<<<(N_NODES + 255) / 256, 256>>>(big[0], big[1], small[0], small[1]);
    fill_convert_kernel<<<(N_EDGES + 255) / 256, 256>>>(big[0], big[1]);
    gather_kernel<<<(N_NODES * 32 + 255) / 256, 256>>>(big[0], big[1]);

    // smem: W 64KB + rowbuf 32KB + scratch 32KB + tids = ~128KB, 1 CTA/SM
    const int smem = SM_TOTAL * (int)sizeof(float);
    cudaFuncSetAttribute(gemm_kernel, cudaFuncAttributeMaxDynamicSharedMemorySize, smem);
    gemm_kernel<<<GEMM_GRID, GEMM_WARPS * 32, smem>>>(W, small[0], small[1], small[2]);

    bn_kernel<<<(BN_CHUNK + 255) / 256, 256>>>(small[0], small[1], small[2], out);
}

// round 16
// speedup vs baseline: 1.2083x; 1.2083x over previous
#include <cuda_runtime.h>
#include <cuda_fp16.h>
#include <mma.h>
using namespace nvcuda;

#define N_NODES 10000
#define N_EDGES 640000
#define D 128
#define BN_EPS 1e-5f
#define CAP 256
#define STRIPS (N_NODES / 16)            // 625
#define GEMM_BLOCKS ((STRIPS + 3) / 4)   // 157, 4 warps each

// Scratch (no allocation allowed anywhere)
__device__ __align__(16) __half g_aggh[N_NODES * D];  // fp16 agg (GEMM A)
__device__ __align__(16) __half g_wh[D * D];          // fp16 W   (GEMM B)
__device__ __align__(16) float  g_h2[N_NODES * D];    // relu(h @ W + b)
__device__ __align__(16) __half g_xh[N_NODES * D];    // fp16 mirror of x
__device__ __align__(16) float  g_colsum[D];
__device__ __align__(16) float  g_colsumsq[D];

__device__ int g_deg[N_NODES];
__device__ int g_bucket[N_NODES * CAP];

__device__ int g_ei_sel;
__device__ int g_ei_64;
__device__ int g_gamma_sel;

// ---------------------------------------------------------------------------
__device__ __forceinline__ int edge_at(const void* eip, int i, int is64) {
    return is64 ? (int)((const long long*)eip)[i] : ((const int*)eip)[i];
}
__device__ __forceinline__ int looks_like_idx32(const int* p) {
    #pragma unroll
    for (int i = 0; i < 32; i++) { int v = p[i]; if (v < 0 || v >= N_NODES) return 0; }
    return 1;
}
__device__ __forceinline__ int looks_like_idx64(const long long* p) {
    #pragma unroll
    for (int i = 0; i < 32; i++) { long long v = p[i]; if (v < 0 || v >= N_NODES) return 0; }
    return 1;
}

// ---------------------------------------------------------------------------
// 1) prep: zero deg/stats, classify inputs, convert W -> fp16
// ---------------------------------------------------------------------------
__global__ void prep_kernel(const void* __restrict__ big0,
                            const void* __restrict__ big1,
                            const float* __restrict__ c0,
                            const float* __restrict__ c1,
                            const float* __restrict__ W) {
    int i = blockIdx.x * blockDim.x + threadIdx.x;
    if (i < N_NODES) g_deg[i] = 0;
    if (i < D) { g_colsum[i] = 0.f; g_colsumsq[i] = 0.f; }
    if (i < D * D / 4) {                       // 4096 threads convert W
        float4 v = ((const float4*)W)[i];
        __half2 h0 = __floats2half2_rn(v.x, v.y);
        __half2 h1 = __floats2half2_rn(v.z, v.w);
        uint2 packed;
        packed.x = *(unsigned*)&h0;
        packed.y = *(unsigned*)&h1;
        ((uint2*)g_wh)[i] = packed;
    }
    if (i == 0) {
        if (looks_like_idx32((const int*)big0))            { g_ei_sel = 0; g_ei_64 = 0; }
        else if (looks_like_idx64((const long long*)big0)) { g_ei_sel = 0; g_ei_64 = 1; }
        else if (looks_like_idx32((const int*)big1))       { g_ei_sel = 1; g_ei_64 = 0; }
        else                                               { g_ei_sel = 1; g_ei_64 = 1; }
        int sel = 2;
        if (fabsf(c0[0] - 1.0f) < 0.25f)      sel = 0;
        else if (fabsf(c1[0] - 1.0f) < 0.25f) sel = 1;
        g_gamma_sel = sel;
    }
}

// ---------------------------------------------------------------------------
// 2) convert x -> fp16 mirror (separate launch: R12-proven faster than merged)
// ---------------------------------------------------------------------------
__global__ void convert_kernel(const void* __restrict__ big0,
                               const void* __restrict__ big1) {
    const float* x = (const float*)((g_ei_sel == 0) ? big1 : big0);
    int i = blockIdx.x * blockDim.x + threadIdx.x;
    const int n4 = N_NODES * D / 4;
    if (i >= n4) return;
    float4 v = ((const float4*)x)[i];
    __half2 h0 = __floats2half2_rn(v.x, v.y);
    __half2 h1 = __floats2half2_rn(v.z, v.w);
    uint2 packed;
    packed.x = *(unsigned*)&h0;
    packed.y = *(unsigned*)&h1;
    ((uint2*)g_xh)[i] = packed;
}

// ---------------------------------------------------------------------------
// 3) fill buckets
// ---------------------------------------------------------------------------
__global__ void fill_kernel(const void* __restrict__ big0,
                            const void* __restrict__ big1) {
    const void* eip = (g_ei_sel == 0) ? big0 : big1;
    const int is64 = g_ei_64;
    int e = blockIdx.x * blockDim.x + threadIdx.x;
    if (e >= N_EDGES) return;
    int s = edge_at(eip, e, is64);
    int d = edge_at(eip, N_EDGES + e, is64);
    s = min(max(s, 0), N_NODES - 1);
    d = min(max(d, 0), N_NODES - 1);
    int pos = atomicAdd(&g_deg[d], 1);
    if (pos < CAP) g_bucket[d * CAP + pos] = s;
}

// ---------------------------------------------------------------------------
// 4) gather -> fp16 agg (f32 accumulation, fp16 store)
// ---------------------------------------------------------------------------
__global__ void gather_kernel(const void* __restrict__ big0,
                              const void* __restrict__ big1) {
    const float* x = (const float*)((g_ei_sel == 0) ? big1 : big0);
    int warp = (blockIdx.x * blockDim.x + threadIdx.x) >> 5;
    int lane = threadIdx.x & 31;
    if (warp >= N_NODES) return;
    const int n   = warp;
    const int cnt = min(g_deg[n], CAP);
    const int* bk = g_bucket + n * CAP;

    float4 acc = ((const float4*)(x + (size_t)n * D))[lane];

    int j = 0;
    for (; j + 32 <= cnt; j += 32) {
        int id = bk[j + lane];
        #pragma unroll
        for (int i = 0; i < 32; i++) {
            int s = __shfl_sync(0xffffffffu, id, i);
            uint2 v = ((const uint2*)(g_xh + (size_t)s * D))[lane];
            float2 f0 = __half22float2(*(__half2*)&v.x);
            float2 f1 = __half22float2(*(__half2*)&v.y);
            acc.x += f0.x; acc.y += f0.y; acc.z += f1.x; acc.w += f1.y;
        }
    }
    if (j < cnt) {
        int rem = cnt - j;
        int id = bk[j + min(lane, rem - 1)];
        for (int i = 0; i < rem; i++) {
            int s = __shfl_sync(0xffffffffu, id, i);
            uint2 v = ((const uint2*)(g_xh + (size_t)s * D))[lane];
            float2 f0 = __half22float2(*(__half2*)&v.x);
            float2 f1 = __half22float2(*(__half2*)&v.y);
            acc.x += f0.x; acc.y += f0.y; acc.z += f1.x; acc.w += f1.y;
        }
    }
    __half2 h0 = __floats2half2_rn(acc.x, acc.y);
    __half2 h1 = __floats2half2_rn(acc.z, acc.w);
    uint2 packed;
    packed.x = *(unsigned*)&h0;
    packed.y = *(unsigned*)&h1;
    ((uint2*)(g_aggh + (size_t)n * D))[lane] = packed;
}

// ---------------------------------------------------------------------------
// 5) tensor-core GEMM: h2 = relu(aggh @ Wh + b), fused BN stats
//    one warp per 16-row strip; 8 f32 accum fragments (full 128 cols)
// ---------------------------------------------------------------------------
__global__ void __launch_bounds__(128)
gemm_kernel(const float* __restrict__ c0,
            const float* __restrict__ c1,
            const float* __restrict__ c2) {
    const int gs = g_gamma_sel;
    const float* b = (gs == 0) ? c1 : c0;

    extern __shared__ char sm[];
    __half* Wsh  = (__half*)sm;                       // 128x128 fp16 = 32KB
    float*  cbuf = (float*)(sm + D * D * 2);          // 4 warps * 16*128 f32 = 32KB

    const int lane = threadIdx.x & 31;
    const int warp = threadIdx.x >> 5;

    for (int i = threadIdx.x; i < D * D / 8; i += blockDim.x)
        ((uint4*)Wsh)[i] = ((const uint4*)g_wh)[i];
    __syncthreads();

    const float4 bias = ((const float4*)b)[lane];
    float4 ssum = make_float4(0.f, 0.f, 0.f, 0.f);
    float4 ssq  = make_float4(0.f, 0.f, 0.f, 0.f);

    const int strip = blockIdx.x * 4 + warp;
    if (strip < STRIPS) {
        wmma::fragment<wmma::accumulator, 16, 16, 16, float> cfrag[8];
        #pragma unroll
        for (int n = 0; n < 8; n++) wmma::fill_fragment(cfrag[n], 0.0f);

        const __half* arow = g_aggh + (size_t)strip * 16 * D;
        #pragma unroll
        for (int k = 0; k < 8; k++) {
            wmma::fragment<wmma::matrix_a, 16, 16, 16, __half, wmma::row_major> afrag;
            wmma::load_matrix_sync(afrag, arow + k * 16, D);
            #pragma unroll
            for (int n = 0; n < 8; n++) {
                wmma::fragment<wmma::matrix_b, 16, 16, 16, __half, wmma::row_major> bfrag;
                wmma::load_matrix_sync(bfrag, Wsh + (k * 16) * D + n * 16, D);
                wmma::mma_sync(cfrag[n], afrag, bfrag, cfrag[n]);
            }
        }

        float* cb = cbuf + warp * 16 * D;
        #pragma unroll
        for (int n = 0; n < 8; n++)
            wmma::store_matrix_sync(cb + n * 16, cfrag[n], D, wmma::mem_row_major);
        __syncwarp();

        // epilogue: lane owns cols [4*lane, 4*lane+3] over 16 rows
        #pragma unroll
        for (int r = 0; r < 16; r++) {
            float4 v = ((const float4*)(cb + r * D))[lane];
            float4 o;
            o.x = fmaxf(v.x + bias.x, 0.f);
            o.y = fmaxf(v.y + bias.y, 0.f);
            o.z = fmaxf(v.z + bias.z, 0.f);
            o.w = fmaxf(v.w + bias.w, 0.f);
            ((float4*)(g_h2 + (size_t)(strip * 16 + r) * D))[lane] = o;
            ssum.x += o.x; ssum.y += o.y; ssum.z += o.z; ssum.w += o.w;
            ssq.x  += o.x * o.x; ssq.y += o.y * o.y;
            ssq.z  += o.z * o.z; ssq.w += o.w * o.w;
        }
    }

    atomicAdd(((float4*)g_colsum) + lane, ssum);
    atomicAdd(((float4*)g_colsumsq) + lane, ssq);
}

// ---------------------------------------------------------------------------
// 6) bn: per-block recompute scale/shift from stats, then apply (R13-measured)
// ---------------------------------------------------------------------------
__global__ void bn_kernel(const float* __restrict__ c0,
                          const float* __restrict__ c1,
                          const float* __restrict__ c2,
                          float* __restrict__ out) {
    __shared__ float s_scale[D], s_shift[D];
    const int gs = g_gamma_sel;
    const float* gamma = (gs == 0) ? c0 : (gs == 1) ? c1 : c2;
    const float* beta  = (gs == 2) ? c1 : c2;

    if (threadIdx.x < D) {
        int j = threadIdx.x;
        float mean = g_colsum[j] * (1.0f / N_NODES);
        float var  = g_colsumsq[j] * (1.0f / N_NODES) - mean * mean;
        float sc   = gamma[j] * rsqrtf(var + BN_EPS);
        s_scale[j] = sc;
        s_shift[j] = beta[j] - mean * sc;
    }
    __syncthreads();

    int i = blockIdx.x * blockDim.x + threadIdx.x;
    const int n4 = N_NODES * D / 4;
    if (i >= n4) return;
    float4 h  = ((const float4*)g_h2)[i];
    int c4    = (i & (D / 4 - 1)) * 4;
    float4 o;
    o.x = h.x * s_scale[c4 + 0] + s_shift[c4 + 0];
    o.y = h.y * s_scale[c4 + 1] + s_shift[c4 + 1];
    o.z = h.z * s_scale[c4 + 2] + s_shift[c4 + 2];
    o.w = h.w * s_scale[c4 + 3] + s_shift[c4 + 3];
    ((float4*)out)[i] = o;
}

// ---------------------------------------------------------------------------
extern "C" void kernel_launch(void* const* d_in, const int* in_sizes, int n_in,
                              void* d_out, int out_size) {
    const void* big[2] = {nullptr, nullptr};
    const float* W = nullptr;
    const float* small[3] = {nullptr, nullptr, nullptr};
    int nbig = 0, nsmall = 0;
    for (int i = 0; i < n_in; i++) {
        int s = in_sizes[i];
        if (s == D * D) {
            W = (const float*)d_in[i];
        } else if (s == D) {
            if (nsmall < 3) small[nsmall++] = (const float*)d_in[i];
        } else if (s >= N_NODES * D) {
            if (nbig < 2) big[nbig++] = d_in[i];
        }
    }
    float* out = (float*)d_out;

    const int n4 = N_NODES * D / 4;
    prep_kernel<<<(N_NODES + 255) / 256, 256>>>(big[0], big[1], small[0], small[1], W);
    convert_kernel<<<(n4 + 255) / 256, 256>>>(big[0], big[1]);
    fill_kernel<<<(N_EDGES + 255) / 256, 256>>>(big[0], big[1]);
    gather_kernel<<<(N_NODES * 32 + 255) / 256, 256>>>(big[0], big[1]);

    // smem: Wh fp16 32KB + 4-warp C buffers 32KB = 64KB
    const int smem = D * D * 2 + 4 * 16 * D * (int)sizeof(float);
    cudaFuncSetAttribute(gemm_kernel, cudaFuncAttributeMaxDynamicSharedMemorySize, smem);
    gemm_kernel<<<GEMM_BLOCKS, 128, smem>>>(small[0], small[1], small[2]);

    bn_kernel<<<(n4 + 255) / 256, 256>>>(small[0], small[1], small[2], out);
}

// round 17
// speedup vs baseline: 1.2231x; 1.0123x over previous
#include <cuda_runtime.h>
#include <cuda_fp16.h>
#include <mma.h>
using namespace nvcuda;

#define N_NODES 10000
#define N_EDGES 640000
#define D 128
#define BN_EPS 1e-5f
#define CAP 256
#define STRIPS ((N_NODES + 15) / 16)     // 625
#define GEMM_BLOCKS ((STRIPS + 3) / 4)   // 157, 4 warps each

// Scratch (no allocation allowed anywhere)
__device__ __align__(16) __half g_aggh[N_NODES * D];  // fp16 agg (GEMM A)
__device__ __align__(16) __half g_wh[D * D];          // fp16 W   (GEMM B)
__device__ __align__(16) float  g_h2[N_NODES * D];    // relu(h @ W + b)
__device__ __align__(16) __half g_xh[N_NODES * D];    // fp16 mirror of x
__device__ __align__(16) float  g_colsum[D];
__device__ __align__(16) float  g_colsumsq[D];

__device__ int g_deg[N_NODES];
__device__ int g_bucket[N_NODES * CAP];

__device__ int g_ei_sel;
__device__ int g_ei_64;
__device__ int g_gamma_sel;

// ---------------------------------------------------------------------------
__device__ __forceinline__ int edge_at(const void* eip, int i, int is64) {
    return is64 ? (int)((const long long*)eip)[i] : ((const int*)eip)[i];
}
__device__ __forceinline__ int looks_like_idx32(const int* p) {
    #pragma unroll
    for (int i = 0; i < 32; i++) { int v = p[i]; if (v < 0 || v >= N_NODES) return 0; }
    return 1;
}
__device__ __forceinline__ int looks_like_idx64(const long long* p) {
    #pragma unroll
    for (int i = 0; i < 32; i++) { long long v = p[i]; if (v < 0 || v >= N_NODES) return 0; }
    return 1;
}

// ---------------------------------------------------------------------------
// 1) prep: zero deg/stats, classify inputs, convert W -> fp16
// ---------------------------------------------------------------------------
__global__ void prep_kernel(const void* __restrict__ big0,
                            const void* __restrict__ big1,
                            const float* __restrict__ c0,
                            const float* __restrict__ c1,
                            const float* __restrict__ W) {
    int i = blockIdx.x * blockDim.x + threadIdx.x;
    if (i < N_NODES) g_deg[i] = 0;
    if (i < D) { g_colsum[i] = 0.f; g_colsumsq[i] = 0.f; }
    if (i < D * D / 4) {
        float4 v = ((const float4*)W)[i];
        __half2 h0 = __floats2half2_rn(v.x, v.y);
        __half2 h1 = __floats2half2_rn(v.z, v.w);
        uint2 packed;
        packed.x = *(unsigned*)&h0;
        packed.y = *(unsigned*)&h1;
        ((uint2*)g_wh)[i] = packed;
    }
    if (i == 0) {
        if (looks_like_idx32((const int*)big0))            { g_ei_sel = 0; g_ei_64 = 0; }
        else if (looks_like_idx64((const long long*)big0)) { g_ei_sel = 0; g_ei_64 = 1; }
        else if (looks_like_idx32((const int*)big1))       { g_ei_sel = 1; g_ei_64 = 0; }
        else                                               { g_ei_sel = 1; g_ei_64 = 1; }
        int sel = 2;
        if (fabsf(c0[0] - 1.0f) < 0.25f)      sel = 0;
        else if (fabsf(c1[0] - 1.0f) < 0.25f) sel = 1;
        g_gamma_sel = sel;
    }
}

// ---------------------------------------------------------------------------
// 2) fill buckets + convert x -> fp16 (merged; R14-proven neutral)
// ---------------------------------------------------------------------------
__global__ void fill_convert_kernel(const void* __restrict__ big0,
                                    const void* __restrict__ big1) {
    const void*  eip = (g_ei_sel == 0) ? big0 : big1;
    const float* x   = (const float*)((g_ei_sel == 0) ? big1 : big0);
    const int is64 = g_ei_64;
    int e = blockIdx.x * blockDim.x + threadIdx.x;

    const int n4 = N_NODES * D / 4;
    if (e < n4) {
        float4 v = ((const float4*)x)[e];
        __half2 h0 = __floats2half2_rn(v.x, v.y);
        __half2 h1 = __floats2half2_rn(v.z, v.w);
        uint2 packed;
        packed.x = *(unsigned*)&h0;
        packed.y = *(unsigned*)&h1;
        ((uint2*)g_xh)[e] = packed;
    }

    if (e >= N_EDGES) return;
    int s = edge_at(eip, e, is64);
    int d = edge_at(eip, N_EDGES + e, is64);
    s = min(max(s, 0), N_NODES - 1);
    d = min(max(d, 0), N_NODES - 1);
    int pos = atomicAdd(&g_deg[d], 1);
    if (pos < CAP) g_bucket[d * CAP + pos] = s;
}

// ---------------------------------------------------------------------------
// 3) gather -> fp16 agg (f32 accumulation, fp16 store)
// ---------------------------------------------------------------------------
__global__ void gather_kernel(const void* __restrict__ big0,
                              const void* __restrict__ big1) {
    const float* x = (const float*)((g_ei_sel == 0) ? big1 : big0);
    int warp = (blockIdx.x * blockDim.x + threadIdx.x) >> 5;
    int lane = threadIdx.x & 31;
    if (warp >= N_NODES) return;
    const int n   = warp;
    const int cnt = min(g_deg[n], CAP);
    const int* bk = g_bucket + n * CAP;

    float4 acc = ((const float4*)(x + (size_t)n * D))[lane];

    int j = 0;
    for (; j + 32 <= cnt; j += 32) {
        int id = bk[j + lane];
        #pragma unroll
        for (int i = 0; i < 32; i++) {
            int s = __shfl_sync(0xffffffffu, id, i);
            uint2 v = ((const uint2*)(g_xh + (size_t)s * D))[lane];
            float2 f0 = __half22float2(*(__half2*)&v.x);
            float2 f1 = __half22float2(*(__half2*)&v.y);
            acc.x += f0.x; acc.y += f0.y; acc.z += f1.x; acc.w += f1.y;
        }
    }
    if (j < cnt) {
        int rem = cnt - j;
        int id = bk[j + min(lane, rem - 1)];
        for (int i = 0; i < rem; i++) {
            int s = __shfl_sync(0xffffffffu, id, i);
            uint2 v = ((const uint2*)(g_xh + (size_t)s * D))[lane];
            float2 f0 = __half22float2(*(__half2*)&v.x);
            float2 f1 = __half22float2(*(__half2*)&v.y);
            acc.x += f0.x; acc.y += f0.y; acc.z += f1.x; acc.w += f1.y;
        }
    }
    __half2 h0 = __floats2half2_rn(acc.x, acc.y);
    __half2 h1 = __floats2half2_rn(acc.z, acc.w);
    uint2 packed;
    packed.x = *(unsigned*)&h0;
    packed.y = *(unsigned*)&h1;
    ((uint2*)(g_aggh + (size_t)n * D))[lane] = packed;
}

// ---------------------------------------------------------------------------
// 4) tensor-core GEMM (launch #4 -> profiled by ncu):
//    block = 4 warps, 4 strips; A staged in smem (coalesced), W in smem
// ---------------------------------------------------------------------------
__global__ void __launch_bounds__(128)
gemm_kernel(const float* __restrict__ c0,
            const float* __restrict__ c1,
            const float* __restrict__ c2) {
    const int gs = g_gamma_sel;
    const float* b = (gs == 0) ? c1 : c0;

    extern __shared__ char sm[];
    __half* Wsh  = (__half*)sm;                        // 128x128 fp16 = 32KB
    __half* Ash  = (__half*)(sm + D * D * 2);          // 64x128 fp16 = 16KB
    float*  cbuf = (float*)(sm + D * D * 2 + 64 * D * 2);  // 4*16*128 f32 = 32KB

    const int lane = threadIdx.x & 31;
    const int warp = threadIdx.x >> 5;
    const int row0 = blockIdx.x * 64;                  // first A row of block

    for (int i = threadIdx.x; i < D * D / 8; i += blockDim.x)
        ((uint4*)Wsh)[i] = ((const uint4*)g_wh)[i];
    // stage up to 64 rows of A (guard tail): 64*16 = 1024 uint4
    {
        int nrows = min(64, N_NODES - row0);
        if (nrows > 0) {
            const uint4* src = (const uint4*)(g_aggh + (size_t)row0 * D);
            for (int i = threadIdx.x; i < nrows * 16; i += blockDim.x)
                ((uint4*)Ash)[i] = src[i];
        }
    }
    __syncthreads();

    const float4 bias = ((const float4*)b)[lane];
    float4 ssum = make_float4(0.f, 0.f, 0.f, 0.f);
    float4 ssq  = make_float4(0.f, 0.f, 0.f, 0.f);

    const int strip = blockIdx.x * 4 + warp;
    if (strip < STRIPS) {
        wmma::fragment<wmma::accumulator, 16, 16, 16, float> cfrag[8];
        #pragma unroll
        for (int n = 0; n < 8; n++) wmma::fill_fragment(cfrag[n], 0.0f);

        const __half* arow = Ash + warp * 16 * D;
        #pragma unroll
        for (int k = 0; k < 8; k++) {
            wmma::fragment<wmma::matrix_a, 16, 16, 16, __half, wmma::row_major> afrag;
            wmma::load_matrix_sync(afrag, arow + k * 16, D);
            #pragma unroll
            for (int n = 0; n < 8; n++) {
                wmma::fragment<wmma::matrix_b, 16, 16, 16, __half, wmma::row_major> bfrag;
                wmma::load_matrix_sync(bfrag, Wsh + (k * 16) * D + n * 16, D);
                wmma::mma_sync(cfrag[n], afrag, bfrag, cfrag[n]);
            }
        }

        float* cb = cbuf + warp * 16 * D;
        #pragma unroll
        for (int n = 0; n < 8; n++)
            wmma::store_matrix_sync(cb + n * 16, cfrag[n], D, wmma::mem_row_major);
        __syncwarp();

        #pragma unroll
        for (int r = 0; r < 16; r++) {
            float4 v = ((const float4*)(cb + r * D))[lane];
            float4 o;
            o.x = fmaxf(v.x + bias.x, 0.f);
            o.y = fmaxf(v.y + bias.y, 0.f);
            o.z = fmaxf(v.z + bias.z, 0.f);
            o.w = fmaxf(v.w + bias.w, 0.f);
            ((float4*)(g_h2 + (size_t)(strip * 16 + r) * D))[lane] = o;
            ssum.x += o.x; ssum.y += o.y; ssum.z += o.z; ssum.w += o.w;
            ssq.x  += o.x * o.x; ssq.y += o.y * o.y;
            ssq.z  += o.z * o.z; ssq.w += o.w * o.w;
        }
    }

    atomicAdd(((float4*)g_colsum) + lane, ssum);
    atomicAdd(((float4*)g_colsumsq) + lane, ssq);
}

// ---------------------------------------------------------------------------
// 5) bn: recompute scale/shift per block; 4 independent float4 per thread
// ---------------------------------------------------------------------------
#define BN_CHUNK (N_NODES * D / 4 / 4)   // 80000 float4 per chunk
__global__ void bn_kernel(const float* __restrict__ c0,
                          const float* __restrict__ c1,
                          const float* __restrict__ c2,
                          float* __restrict__ out) {
    __shared__ float s_scale[D], s_shift[D];
    const int gs = g_gamma_sel;
    const float* gamma = (gs == 0) ? c0 : (gs == 1) ? c1 : c2;
    const float* beta  = (gs == 2) ? c1 : c2;

    if (threadIdx.x < D) {
        int j = threadIdx.x;
        float mean = g_colsum[j] * (1.0f / N_NODES);
        float var  = g_colsumsq[j] * (1.0f / N_NODES) - mean * mean;
        float sc   = gamma[j] * rsqrtf(var + BN_EPS);
        s_scale[j] = sc;
        s_shift[j] = beta[j] - mean * sc;
    }
    __syncthreads();

    int i = blockIdx.x * blockDim.x + threadIdx.x;
    if (i >= BN_CHUNK) return;
    int c4 = (i & (D / 4 - 1)) * 4;      // BN_CHUNK multiple of 32 -> same cols
    float sx = s_scale[c4 + 0], sy = s_scale[c4 + 1],
          sz = s_scale[c4 + 2], sw = s_scale[c4 + 3];
    float tx = s_shift[c4 + 0], ty = s_shift[c4 + 1],
          tz = s_shift[c4 + 2], tw = s_shift[c4 + 3];
    #pragma unroll
    for (int q = 0; q < 4; q++) {
        int idx = i + q * BN_CHUNK;
        float4 hv = ((const float4*)g_h2)[idx];
        float4 o;
        o.x = hv.x * sx + tx;
        o.y = hv.y * sy + ty;
        o.z = hv.z * sz + tz;
        o.w = hv.w * sw + tw;
        ((float4*)out)[idx] = o;
    }
}

// ---------------------------------------------------------------------------
extern "C" void kernel_launch(void* const* d_in, const int* in_sizes, int n_in,
                              void* d_out, int out_size) {
    const void* big[2] = {nullptr, nullptr};
    const float* W = nullptr;
    const float* small[3] = {nullptr, nullptr, nullptr};
    int nbig = 0, nsmall = 0;
    for (int i = 0; i < n_in; i++) {
        int s = in_sizes[i];
        if (s == D * D) {
            W = (const float*)d_in[i];
        } else if (s == D) {
            if (nsmall < 3) small[nsmall++] = (const float*)d_in[i];
        } else if (s >= N_NODES * D) {
            if (nbig < 2) big[nbig++] = d_in[i];
        }
    }
    float* out = (float*)d_out;

    prep_kernel<<<(N_NODES + 255) / 256, 256>>>(big[0], big[1], small[0], small[1], W);
    fill_convert_kernel<<<(N_EDGES + 255) / 256, 256>>>(big[0], big[1]);
    gather_kernel<<<(N_NODES * 32 + 255) / 256, 256>>>(big[0], big[1]);

    // smem: Wh 32KB + Ash 16KB + cbuf 32KB = 80KB
    const int smem = D * D * 2 + 64 * D * 2 + 4 * 16 * D * (int)sizeof(float);
    cudaFuncSetAttribute(gemm_kernel, cudaFuncAttributeMaxDynamicSharedMemorySize, smem);
    gemm_kernel<<<GEMM_BLOCKS, 128, smem>>>(small[0], small[1], small[2]);

    bn_kernel<<<(BN_CHUNK + 255) / 256, 256>>>(small[0], small[1], small[2], out);
}